// round 13
// baseline (speedup 1.0000x reference)
#include <cuda_runtime.h>
#include <cuda_fp16.h>

// Problem constants
#define BATCH   4
#define T_SEQ   2048
#define CDIM    384
#define HEADS   6
#define DH      64
#define MROWS   (BATCH * T_SEQ)        // 8192

typedef unsigned int u32;

// Q pre-scale: 1/sqrt(64) * log2(e)  (base-2 softmax)
#define QSCALE (0.125f * 1.4426950408889634f)
#define ONES_H2 0x3C003C00u            // fp16 {1.0, 1.0}

// ---------------- scratch (static device globals; no runtime allocation) ----
__device__ __half g_xh[MROWS * CDIM];               // x in fp16
__device__ __half g_wh[4][CDIM * CDIM];             // Wq,Wk,Wv,Wo in fp16
__device__ __half g_q[BATCH * HEADS * T_SEQ * DH];  // [B,H,T,D], pre-scaled
__device__ __half g_k[BATCH * HEADS * T_SEQ * DH];
__device__ __half g_v[BATCH * HEADS * T_SEQ * DH];
__device__ __half g_ctx[MROWS * CDIM];              // [B*T, C] fp16

// ---------------- primitives ------------------------------------------------
__device__ __forceinline__ u32 pack_h2(float lo, float hi) {
    u32 r;
    asm("cvt.rn.f16x2.f32 %0, %1, %2;" : "=r"(r) : "f"(hi), "f"(lo));
    return r;
}
__device__ __forceinline__ float ex2f(float x) {
    float y;
    asm("ex2.approx.f32 %0, %1;" : "=f"(y) : "f"(x));
    return y;
}
__device__ __forceinline__ u32 ex2h2(u32 x) {
    u32 y;
    asm("ex2.approx.f16x2 %0, %1;" : "=r"(y) : "r"(x));
    return y;
}

__device__ __forceinline__ void mma_f16(float c[4], const u32 a[4], u32 b0, u32 b1) {
    asm volatile(
        "mma.sync.aligned.m16n8k16.row.col.f32.f16.f16.f32 "
        "{%0,%1,%2,%3}, {%4,%5,%6,%7}, {%8,%9}, {%0,%1,%2,%3};\n"
        : "+f"(c[0]), "+f"(c[1]), "+f"(c[2]), "+f"(c[3])
        : "r"(a[0]), "r"(a[1]), "r"(a[2]), "r"(a[3]), "r"(b0), "r"(b1));
}

__device__ __forceinline__ void ldm_x4(u32& r0, u32& r1, u32& r2, u32& r3, u32 addr) {
    asm volatile("ldmatrix.sync.aligned.m8n8.x4.shared.b16 {%0,%1,%2,%3}, [%4];"
                 : "=r"(r0), "=r"(r1), "=r"(r2), "=r"(r3) : "r"(addr));
}
__device__ __forceinline__ void ldm_x4t(u32& r0, u32& r1, u32& r2, u32& r3, u32 addr) {
    asm volatile("ldmatrix.sync.aligned.m8n8.x4.trans.shared.b16 {%0,%1,%2,%3}, [%4];"
                 : "=r"(r0), "=r"(r1), "=r"(r2), "=r"(r3) : "r"(addr));
}

__device__ __forceinline__ void cp_async16(u32 saddr, const void* gptr) {
    asm volatile("cp.async.cg.shared.global [%0], [%1], 16;" :: "r"(saddr), "l"(gptr));
}
__device__ __forceinline__ void cp_commit() { asm volatile("cp.async.commit_group;"); }
__device__ __forceinline__ void cp_wait1()  { asm volatile("cp.async.wait_group 1;"); }
__device__ __forceinline__ void cp_wait0()  { asm volatile("cp.async.wait_group 0;"); }

// ---------------- fp32 -> fp16 converters -----------------------------------
__global__ __launch_bounds__(256) void cvt_x_kernel(const float* __restrict__ in,
                                                    __half* __restrict__ out) {
    int i = (blockIdx.x * 256 + threadIdx.x) * 4;
    float4 v = *reinterpret_cast<const float4*>(in + i);
    *reinterpret_cast<uint2*>(out + i) =
        make_uint2(pack_h2(v.x, v.y), pack_h2(v.z, v.w));
}
__global__ __launch_bounds__(256) void cvt_w_kernel(
    const float* __restrict__ w0, const float* __restrict__ w1,
    const float* __restrict__ w2, const float* __restrict__ w3,
    __half* __restrict__ out) {
    const float* src = (blockIdx.y == 0) ? w0 : (blockIdx.y == 1) ? w1
                     : (blockIdx.y == 2) ? w2 : w3;
    int i = (blockIdx.x * 256 + threadIdx.x) * 4;
    float4 v = *reinterpret_cast<const float4*>(src + i);
    *reinterpret_cast<uint2*>(out + blockIdx.y * (CDIM * CDIM) + i) =
        make_uint2(pack_h2(v.x, v.y), pack_h2(v.z, v.w));
}

// ---------------- fp16 GEMM core: cp.async 3-stage, 128x128 tile, BK=32 -----
#define AS_LD 40    // halfs
#define WS_LD 136   // halfs
#define A_STAGE (128 * AS_LD)   // 5120 halfs
#define W_STAGE (32 * WS_LD)    // 4352 halfs
#define GEMM_SMEM_BYTES (3 * (A_STAGE + W_STAGE) * 2)   // 56832

template <typename EPI>
__device__ __forceinline__ void gemm_core_h(
    const __half* __restrict__ A, const __half* __restrict__ W,
    int K, int N, int m0, int n0, EPI epi)
{
    extern __shared__ __half sh[];
    __half* As = sh;
    __half* Ws = sh + 3 * A_STAGE;

    const int tid  = threadIdx.x;
    const int lane = tid & 31;
    const int w    = tid >> 5;
    const int gid  = lane >> 2;
    const int tig  = lane & 3;
    const int wm0  = (w & 1) * 64;
    const int wn0  = (w >> 1) * 32;
    const u32 as_base = (u32)__cvta_generic_to_shared(As);
    const u32 ws_base = (u32)__cvta_generic_to_shared(Ws);

    const int a_id = lane >> 3;
    const int a_r  = lane & 7;
    const int a_row_off = (a_id & 1) * 8 + a_r;
    const int a_col_off = (a_id >> 1) * 8;

    float acc[4][4][4];
#pragma unroll
    for (int mt = 0; mt < 4; mt++)
#pragma unroll
        for (int nt = 0; nt < 4; nt++)
#pragma unroll
            for (int j = 0; j < 4; j++) acc[mt][nt][j] = 0.f;

    auto issue = [&](int kt) {
        const int st = kt % 3;
        const __half* Ab = A + (size_t)m0 * K + kt * 32;
        const __half* Wb = W + (size_t)(kt * 32) * N + n0;
#pragma unroll
        for (int p = 0; p < 2; p++) {
            int id = tid + 256 * p;
            int arw = id >> 2, ac = id & 3;
            cp_async16(as_base + (st * A_STAGE + arw * AS_LD + ac * 8) * 2,
                       Ab + (size_t)arw * K + ac * 8);
            int wrw = id >> 4, wc = id & 15;
            cp_async16(ws_base + (st * W_STAGE + wrw * WS_LD + wc * 8) * 2,
                       Wb + (size_t)wrw * N + wc * 8);
        }
        cp_commit();
    };

    issue(0);
    issue(1);

    const int niter = K / 32;
    for (int kt = 0; kt < niter; kt++) {
        if (kt + 2 <= niter) cp_wait1(); else cp_wait0();
        __syncthreads();
        if (kt + 2 < niter) issue(kt + 2);

        const int st = kt % 3;
        const u32 a_st = as_base + st * A_STAGE * 2;
        const u32 w_st = ws_base + st * W_STAGE * 2;

#pragma unroll
        for (int ks = 0; ks < 2; ks++) {
            u32 af[4][4];
#pragma unroll
            for (int mt = 0; mt < 4; mt++) {
                u32 addr = a_st +
                    ((wm0 + mt * 16 + a_row_off) * AS_LD + ks * 16 + a_col_off) * 2;
                ldm_x4(af[mt][0], af[mt][1], af[mt][2], af[mt][3], addr);
            }
            u32 b0[4], b1[4];
#pragma unroll
            for (int nb = 0; nb < 2; nb++) {
                u32 addr = w_st +
                    ((16 * ks + (lane & 15)) * WS_LD + wn0 + 16 * nb + (lane >> 4) * 8) * 2;
                ldm_x4t(b0[2 * nb], b1[2 * nb], b0[2 * nb + 1], b1[2 * nb + 1], addr);
            }
#pragma unroll
            for (int mt = 0; mt < 4; mt++)
#pragma unroll
                for (int nt = 0; nt < 4; nt++)
                    mma_f16(acc[mt][nt], af[mt], b0[nt], b1[nt]);
        }
    }
    epi(acc, wm0, wn0, gid, tig);
}

// ---------------- merged QKV projection (one launch, grid 9 x 64) -----------
__global__ __launch_bounds__(256, 2) void gemm_qkv_kernel(
    const float* __restrict__ bq, const float* __restrict__ bk,
    const float* __restrict__ bv,
    __half* __restrict__ qp, __half* __restrict__ kp, __half* __restrict__ vp)
{
    const int sel = blockIdx.x / 3;
    const int n0  = (blockIdx.x % 3) * 128;
    const int m0  = blockIdx.y * 128;
    const float* bias = (sel == 0) ? bq : ((sel == 1) ? bk : bv);
    __half* out       = (sel == 0) ? qp : ((sel == 1) ? kp : vp);
    const float oscale = (sel == 0) ? QSCALE : 1.0f;

    gemm_core_h(g_xh, g_wh[sel], CDIM, CDIM, m0, n0,
        [&](float acc[4][4][4], int wm0, int wn0, int gid, int tig) {
#pragma unroll
            for (int mt = 0; mt < 4; mt++) {
#pragma unroll
                for (int half = 0; half < 2; half++) {
                    const int m = m0 + wm0 + mt * 16 + gid + half * 8;
#pragma unroll
                    for (int nt = 0; nt < 4; nt++) {
                        const int n = n0 + wn0 + nt * 8 + 2 * tig;
                        float vx = (acc[mt][nt][half * 2 + 0] + bias[n + 0]) * oscale;
                        float vy = (acc[mt][nt][half * 2 + 1] + bias[n + 1]) * oscale;
                        const int b = m >> 11, t = m & 2047;
                        const int h = n >> 6, d = n & 63;
                        *reinterpret_cast<u32*>(
                            &out[(((size_t)(b * HEADS + h) * T_SEQ + t) * DH) + d]) =
                            pack_h2(vx, vy);
                    }
                }
            }
        });
}

// ---------------- output projection: A=ctx fp16, out float [M,N] ------------
__global__ __launch_bounds__(256, 2) void gemm_out_kernel(
    const float* __restrict__ bias, float* __restrict__ out)
{
    const int n0 = blockIdx.x * 128;
    const int m0 = blockIdx.y * 128;

    gemm_core_h(g_ctx, g_wh[3], CDIM, CDIM, m0, n0,
        [&](float acc[4][4][4], int wm0, int wn0, int gid, int tig) {
#pragma unroll
            for (int mt = 0; mt < 4; mt++) {
#pragma unroll
                for (int half = 0; half < 2; half++) {
                    const int m = m0 + wm0 + mt * 16 + gid + half * 8;
#pragma unroll
                    for (int nt = 0; nt < 4; nt++) {
                        const int n = n0 + wn0 + nt * 8 + 2 * tig;
                        *reinterpret_cast<float2*>(&out[(size_t)m * CDIM + n]) =
                            make_float2(acc[mt][nt][half * 2 + 0] + bias[n + 0],
                                        acc[mt][nt][half * 2 + 1] + bias[n + 1]);
                    }
                }
            }
        });
}

// ---------------- fp16 tensor-core causal flash attention -------------------
// 512 threads / 16 warps. BQ=128; each 128-key round is split between two
// warp groups (wkey = w>>3): group g owns keys [k0+64g, k0+64g+64), with its
// OWN online-softmax state (m, l, O). One smem merge at the end recombines.
// 3-stage cp.async ring of 128-key stages; ring smem reused for the merge.
#define BQ 128
#define RK 128                        // keys per round (64 per warp group)
#define KS_LD 72   // halfs
#define VS_LD 72
#define STAGE_HALFS (RK * KS_LD + RK * VS_LD)       // 18432
#define ATTN_SMEM_BYTES (3 * STAGE_HALFS * 2)       // 110592

__global__ void __launch_bounds__(512, 1) attn_kernel(__half* __restrict__ ctx)
{
    extern __shared__ __half smh[];

    const int tid  = threadIdx.x;
    const int lane = tid & 31;
    const int w    = tid >> 5;           // 0..15
    const int wkey = w >> 3;             // key-half group 0/1
    const int wrow = w & 7;              // row-owner 0..7
    const int gid  = lane >> 2;
    const int tig  = lane & 3;

    const int bh = blockIdx.y;
    const int qi = gridDim.x - 1 - blockIdx.x;   // heavy blocks first
    const int q0 = qi * BQ;

    const __half* qb = g_q + (size_t)bh * T_SEQ * DH;
    const __half* kb = g_k + (size_t)bh * T_SEQ * DH;
    const __half* vb = g_v + (size_t)bh * T_SEQ * DH;

    // ---- Q A-frags straight from gmem (both key-groups load same rows) ----
    const int arow = wrow * 16 + gid;
    u32 qf[4][4];
#pragma unroll
    for (int s = 0; s < 4; s++) {
        const __half* base = &qb[(size_t)(q0 + arow) * DH + s * 16 + 2 * tig];
        qf[s][0] = *reinterpret_cast<const u32*>(base);
        qf[s][1] = *reinterpret_cast<const u32*>(base + 8 * DH);
        qf[s][2] = *reinterpret_cast<const u32*>(base + 8);
        qf[s][3] = *reinterpret_cast<const u32*>(base + 8 * DH + 8);
    }

    float O[8][4];
#pragma unroll
    for (int nt = 0; nt < 8; nt++)
#pragma unroll
        for (int j = 0; j < 4; j++) O[nt][j] = 0.f;
    float OS[4] = {0.f, 0.f, 0.f, 0.f};   // row-sum accumulator (l) via mma
    float mA = -1e30f, mB = -1e30f;

    const u32 smbase = (u32)__cvta_generic_to_shared(smh);
    u32 kbase[3], vbase[3];
#pragma unroll
    for (int s = 0; s < 3; s++) {
        kbase[s] = smbase + (s * STAGE_HALFS) * 2;
        vbase[s] = kbase[s] + (RK * KS_LD) * 2;
    }
    const u32 grp_off = (u32)(wkey * 64);   // row offset of this group's keys

    const int nrounds = qi + 1;

    // cp.async: 128 rows x 8 chunks per tensor per round; 512 thr -> 2+2 each
    auto issue = [&](int r) {
        const int st = r % 3;
        const __half* kbr = kb + (size_t)(r * RK) * DH;
        const __half* vbr = vb + (size_t)(r * RK) * DH;
#pragma unroll
        for (int p = 0; p < 2; p++) {
            int id = tid + 512 * p;          // 0..1023
            int row = id >> 3, c = id & 7;   // 128 rows x 8 chunks
            cp_async16(kbase[st] + (row * KS_LD + c * 8) * 2,
                       kbr + (size_t)row * DH + c * 8);
            cp_async16(vbase[st] + (row * VS_LD + c * 8) * 2,
                       vbr + (size_t)row * DH + c * 8);
        }
        cp_commit();
    };

    issue(0);
    if (nrounds > 1) issue(1);

    for (int r = 0; r < nrounds; r++) {
        const int k0g = r * RK + wkey * 64;   // this group's first key
        if (r + 2 <= nrounds) cp_wait1(); else cp_wait0();
        __syncthreads();
        if (r + 2 < nrounds) issue(r + 2);

        const int buf = r % 3;

        if (k0g <= q0 + wrow * 16 + 15) {   // group not entirely above diag
            // ---- S = Q K^T over this group's 64 keys ----
            float S[8][4];
#pragma unroll
            for (int nt = 0; nt < 8; nt++)
#pragma unroll
                for (int j = 0; j < 4; j++) S[nt][j] = 0.f;
#pragma unroll
            for (int s = 0; s < 4; s++) {
#pragma unroll
                for (int p = 0; p < 4; p++) {
                    u32 r0, r1, r2, r3;
                    u32 addr = kbase[buf] +
                        (((grp_off + 16 * p + (lane & 15)) * KS_LD) +
                         16 * s + (lane >> 4) * 8) * 2;
                    ldm_x4(r0, r1, r2, r3, addr);
                    mma_f16(S[2 * p],     qf[s], r0, r2);
                    mma_f16(S[2 * p + 1], qf[s], r1, r3);
                }
            }

            // ---- causal mask ----
            const int rA = q0 + arow;
            const int rB = rA + 8;
            if (k0g + 63 > rA) {
#pragma unroll
                for (int nt = 0; nt < 8; nt++) {
                    const int c0 = k0g + nt * 8 + 2 * tig;
                    if (c0     > rA) S[nt][0] = -1e30f;
                    if (c0 + 1 > rA) S[nt][1] = -1e30f;
                    if (c0     > rB) S[nt][2] = -1e30f;
                    if (c0 + 1 > rB) S[nt][3] = -1e30f;
                }
            }

            // ---- online softmax (base 2), group-private state ----
            float mxA = -1e30f, mxB = -1e30f;
#pragma unroll
            for (int nt = 0; nt < 8; nt++) {
                mxA = fmaxf(mxA, fmaxf(S[nt][0], S[nt][1]));
                mxB = fmaxf(mxB, fmaxf(S[nt][2], S[nt][3]));
            }
            mxA = fmaxf(mxA, __shfl_xor_sync(0xffffffffu, mxA, 1));
            mxA = fmaxf(mxA, __shfl_xor_sync(0xffffffffu, mxA, 2));
            mxB = fmaxf(mxB, __shfl_xor_sync(0xffffffffu, mxB, 1));
            mxB = fmaxf(mxB, __shfl_xor_sync(0xffffffffu, mxB, 2));

            const float mnA = fmaxf(mA, mxA), mnB = fmaxf(mB, mxB);
            const float aA = ex2f(mA - mnA), aB = ex2f(mB - mnB);
            mA = mnA;  mB = mnB;
#pragma unroll
            for (int nt = 0; nt < 8; nt++) {
                O[nt][0] *= aA; O[nt][1] *= aA;
                O[nt][2] *= aB; O[nt][3] *= aB;
            }
            OS[0] *= aA; OS[1] *= aA; OS[2] *= aB; OS[3] *= aB;

            // ---- P = 2^(S - mn): pack f32 diffs, ex2 in f16x2 ----
            u32 pa[4][4];
#pragma unroll
            for (int s2 = 0; s2 < 4; s2++) {
                pa[s2][0] = ex2h2(pack_h2(S[2 * s2][0] - mnA, S[2 * s2][1] - mnA));
                pa[s2][1] = ex2h2(pack_h2(S[2 * s2][2] - mnB, S[2 * s2][3] - mnB));
                pa[s2][2] = ex2h2(pack_h2(S[2 * s2 + 1][0] - mnA, S[2 * s2 + 1][1] - mnA));
                pa[s2][3] = ex2h2(pack_h2(S[2 * s2 + 1][2] - mnB, S[2 * s2 + 1][3] - mnB));
            }

            // ---- O += P V ; OS += P @ ones (row sums) ----
#pragma unroll
            for (int s2 = 0; s2 < 4; s2++) {
#pragma unroll
                for (int nb = 0; nb < 4; nb++) {
                    u32 r0, r1, r2, r3;
                    u32 addr = vbase[buf] +
                        (((grp_off + 16 * s2 + (lane & 15)) * VS_LD) +
                         16 * nb + (lane >> 4) * 8) * 2;
                    ldm_x4t(r0, r1, r2, r3, addr);
                    mma_f16(O[2 * nb],     pa[s2], r0, r1);
                    mma_f16(O[2 * nb + 1], pa[s2], r2, r3);
                }
                mma_f16(OS, pa[s2], ONES_H2, ONES_H2);
            }
        }
    }

    // ---- merge the two key-group halves (ring smem is dead now) ----
    __syncthreads();
    float* ms = reinterpret_cast<float*>(smh);
    float* slot = ms + ((size_t)(wrow * 32 + lane)) * 36;
    if (wkey == 1) {
#pragma unroll
        for (int nt = 0; nt < 8; nt++)
#pragma unroll
            for (int j = 0; j < 4; j++) slot[nt * 4 + j] = O[nt][j];
        slot[32] = mA; slot[33] = mB; slot[34] = OS[0]; slot[35] = OS[2];
    }
    __syncthreads();

    if (wkey == 0) {
        const float m1A = slot[32], m1B = slot[33];
        const float l1A = slot[34], l1B = slot[35];
        const float msA = fmaxf(mA, m1A), msB = fmaxf(mB, m1B);
        const float c0A = ex2f(mA - msA),  c1A = ex2f(m1A - msA);
        const float c0B = ex2f(mB - msB),  c1B = ex2f(m1B - msB);
        const float lA = OS[0] * c0A + l1A * c1A;
        const float lB = OS[2] * c0B + l1B * c1B;
        const float iA = 1.f / lA, iB = 1.f / lB;

        const int b = bh / HEADS, h = bh % HEADS;
        const size_t rowA = (size_t)(b * T_SEQ + q0 + arow) * CDIM + h * DH;
        const size_t rowB = rowA + (size_t)8 * CDIM;
#pragma unroll
        for (int nt = 0; nt < 8; nt++) {
            float o0 = (O[nt][0] * c0A + slot[nt * 4 + 0] * c1A) * iA;
            float o1 = (O[nt][1] * c0A + slot[nt * 4 + 1] * c1A) * iA;
            float o2 = (O[nt][2] * c0B + slot[nt * 4 + 2] * c1B) * iB;
            float o3 = (O[nt][3] * c0B + slot[nt * 4 + 3] * c1B) * iB;
            *reinterpret_cast<u32*>(&ctx[rowA + nt * 8 + 2 * tig]) = pack_h2(o0, o1);
            *reinterpret_cast<u32*>(&ctx[rowB + nt * 8 + 2 * tig]) = pack_h2(o2, o3);
        }
    }
}

// ---------------- launch ----------------------------------------------------
extern "C" void kernel_launch(void* const* d_in, const int* in_sizes, int n_in,
                              void* d_out, int out_size)
{
    (void)in_sizes; (void)n_in; (void)out_size;
    const float* x  = (const float*)d_in[0];
    const float* Wq = (const float*)d_in[1];
    const float* bq = (const float*)d_in[2];
    const float* Wk = (const float*)d_in[3];
    const float* bk = (const float*)d_in[4];
    const float* Wv = (const float*)d_in[5];
    const float* bv = (const float*)d_in[6];
    const float* Wo = (const float*)d_in[7];
    const float* bo = (const float*)d_in[8];
    float* out = (float*)d_out;

    static __half *xh = nullptr, *wh = nullptr, *qp = nullptr, *kp = nullptr,
                  *vp = nullptr, *cp = nullptr;
    if (!xh) {
        cudaGetSymbolAddress((void**)&xh, g_xh);
        cudaGetSymbolAddress((void**)&wh, g_wh);
        cudaGetSymbolAddress((void**)&qp, g_q);
        cudaGetSymbolAddress((void**)&kp, g_k);
        cudaGetSymbolAddress((void**)&vp, g_v);
        cudaGetSymbolAddress((void**)&cp, g_ctx);
        cudaFuncSetAttribute(attn_kernel,
                             cudaFuncAttributeMaxDynamicSharedMemorySize,
                             ATTN_SMEM_BYTES);
        cudaFuncSetAttribute(gemm_qkv_kernel,
                             cudaFuncAttributeMaxDynamicSharedMemorySize,
                             GEMM_SMEM_BYTES);
        cudaFuncSetAttribute(gemm_out_kernel,
                             cudaFuncAttributeMaxDynamicSharedMemorySize,
                             GEMM_SMEM_BYTES);
    }

    // fp32 -> fp16 converts
    cvt_x_kernel<<<MROWS * CDIM / 1024, 256>>>(x, xh);
    dim3 wgrid(CDIM * CDIM / 1024, 4);
    cvt_w_kernel<<<wgrid, 256>>>(Wq, Wk, Wv, Wo, wh);

    // merged QKV projection: grid (9, 64)
    dim3 qkvgrid(9, MROWS / 128);
    gemm_qkv_kernel<<<qkvgrid, 256, GEMM_SMEM_BYTES>>>(bq, bk, bv, qp, kp, vp);

    dim3 agrid(T_SEQ / BQ, BATCH * HEADS);   // (16, 24)
    attn_kernel<<<agrid, 512, ATTN_SMEM_BYTES>>>(cp);

    dim3 ogrid(CDIM / 128, MROWS / 128);     // (3, 64)
    gemm_out_kernel<<<ogrid, 256, GEMM_SMEM_BYTES>>>(bo, out);
}

// round 15
// speedup vs baseline: 1.0206x; 1.0206x over previous
#include <cuda_runtime.h>
#include <cuda_fp16.h>

// Problem constants
#define BATCH   4
#define T_SEQ   2048
#define CDIM    384
#define HEADS   6
#define DH      64
#define MROWS   (BATCH * T_SEQ)        // 8192

typedef unsigned int u32;

// Q pre-scale: 1/sqrt(64) * log2(e)  (base-2 softmax)
#define QSCALE (0.125f * 1.4426950408889634f)
#define ONES_H2 0x3C003C00u            // fp16 {1.0, 1.0}

// ---------------- scratch (static device globals; no runtime allocation) ----
__device__ __half g_xh[MROWS * CDIM];               // x in fp16
__device__ __half g_wh[4][CDIM * CDIM];             // Wq,Wk,Wv,Wo in fp16
__device__ __half g_q[BATCH * HEADS * T_SEQ * DH];  // [B,H,T,D], pre-scaled
__device__ __half g_k[BATCH * HEADS * T_SEQ * DH];
__device__ __half g_v[BATCH * HEADS * T_SEQ * DH];
__device__ __half g_ctx[MROWS * CDIM];              // [B*T, C] fp16

// ---------------- primitives ------------------------------------------------
__device__ __forceinline__ u32 pack_h2(float lo, float hi) {
    u32 r;
    asm("cvt.rn.f16x2.f32 %0, %1, %2;" : "=r"(r) : "f"(hi), "f"(lo));
    return r;
}
__device__ __forceinline__ float ex2f(float x) {
    float y;
    asm("ex2.approx.f32 %0, %1;" : "=f"(y) : "f"(x));
    return y;
}
__device__ __forceinline__ u32 ex2h2(u32 x) {
    u32 y;
    asm("ex2.approx.f16x2 %0, %1;" : "=r"(y) : "r"(x));
    return y;
}

__device__ __forceinline__ void mma_f16(float c[4], const u32 a[4], u32 b0, u32 b1) {
    asm volatile(
        "mma.sync.aligned.m16n8k16.row.col.f32.f16.f16.f32 "
        "{%0,%1,%2,%3}, {%4,%5,%6,%7}, {%8,%9}, {%0,%1,%2,%3};\n"
        : "+f"(c[0]), "+f"(c[1]), "+f"(c[2]), "+f"(c[3])
        : "r"(a[0]), "r"(a[1]), "r"(a[2]), "r"(a[3]), "r"(b0), "r"(b1));
}

__device__ __forceinline__ void ldm_x4(u32& r0, u32& r1, u32& r2, u32& r3, u32 addr) {
    asm volatile("ldmatrix.sync.aligned.m8n8.x4.shared.b16 {%0,%1,%2,%3}, [%4];"
                 : "=r"(r0), "=r"(r1), "=r"(r2), "=r"(r3) : "r"(addr));
}
__device__ __forceinline__ void ldm_x4t(u32& r0, u32& r1, u32& r2, u32& r3, u32 addr) {
    asm volatile("ldmatrix.sync.aligned.m8n8.x4.trans.shared.b16 {%0,%1,%2,%3}, [%4];"
                 : "=r"(r0), "=r"(r1), "=r"(r2), "=r"(r3) : "r"(addr));
}

__device__ __forceinline__ void cp_async16(u32 saddr, const void* gptr) {
    asm volatile("cp.async.cg.shared.global [%0], [%1], 16;" :: "r"(saddr), "l"(gptr));
}
__device__ __forceinline__ void cp_commit() { asm volatile("cp.async.commit_group;"); }
__device__ __forceinline__ void cp_wait1()  { asm volatile("cp.async.wait_group 1;"); }
__device__ __forceinline__ void cp_wait0()  { asm volatile("cp.async.wait_group 0;"); }

// ---------------- fp32 -> fp16 converters -----------------------------------
__global__ __launch_bounds__(256) void cvt_x_kernel(const float* __restrict__ in,
                                                    __half* __restrict__ out) {
    int i = (blockIdx.x * 256 + threadIdx.x) * 4;
    float4 v = *reinterpret_cast<const float4*>(in + i);
    *reinterpret_cast<uint2*>(out + i) =
        make_uint2(pack_h2(v.x, v.y), pack_h2(v.z, v.w));
}
__global__ __launch_bounds__(256) void cvt_w_kernel(
    const float* __restrict__ w0, const float* __restrict__ w1,
    const float* __restrict__ w2, const float* __restrict__ w3,
    __half* __restrict__ out) {
    const float* src = (blockIdx.y == 0) ? w0 : (blockIdx.y == 1) ? w1
                     : (blockIdx.y == 2) ? w2 : w3;
    int i = (blockIdx.x * 256 + threadIdx.x) * 4;
    float4 v = *reinterpret_cast<const float4*>(src + i);
    *reinterpret_cast<uint2*>(out + blockIdx.y * (CDIM * CDIM) + i) =
        make_uint2(pack_h2(v.x, v.y), pack_h2(v.z, v.w));
}

// ---------------- fp16 GEMM core: cp.async 3-stage, 128x128 tile, BK=32 -----
#define AS_LD 40    // halfs
#define WS_LD 136   // halfs
#define A_STAGE (128 * AS_LD)   // 5120 halfs
#define W_STAGE (32 * WS_LD)    // 4352 halfs
#define GEMM_SMEM_BYTES (3 * (A_STAGE + W_STAGE) * 2)   // 56832

template <typename EPI>
__device__ __forceinline__ void gemm_core_h(
    const __half* __restrict__ A, const __half* __restrict__ W,
    int K, int N, int m0, int n0, EPI epi)
{
    extern __shared__ __half sh[];
    __half* As = sh;
    __half* Ws = sh + 3 * A_STAGE;

    const int tid  = threadIdx.x;
    const int lane = tid & 31;
    const int w    = tid >> 5;
    const int gid  = lane >> 2;
    const int tig  = lane & 3;
    const int wm0  = (w & 1) * 64;
    const int wn0  = (w >> 1) * 32;
    const u32 as_base = (u32)__cvta_generic_to_shared(As);
    const u32 ws_base = (u32)__cvta_generic_to_shared(Ws);

    const int a_id = lane >> 3;
    const int a_r  = lane & 7;
    const int a_row_off = (a_id & 1) * 8 + a_r;
    const int a_col_off = (a_id >> 1) * 8;

    float acc[4][4][4];
#pragma unroll
    for (int mt = 0; mt < 4; mt++)
#pragma unroll
        for (int nt = 0; nt < 4; nt++)
#pragma unroll
            for (int j = 0; j < 4; j++) acc[mt][nt][j] = 0.f;

    auto issue = [&](int kt) {
        const int st = kt % 3;
        const __half* Ab = A + (size_t)m0 * K + kt * 32;
        const __half* Wb = W + (size_t)(kt * 32) * N + n0;
#pragma unroll
        for (int p = 0; p < 2; p++) {
            int id = tid + 256 * p;
            int arw = id >> 2, ac = id & 3;
            cp_async16(as_base + (st * A_STAGE + arw * AS_LD + ac * 8) * 2,
                       Ab + (size_t)arw * K + ac * 8);
            int wrw = id >> 4, wc = id & 15;
            cp_async16(ws_base + (st * W_STAGE + wrw * WS_LD + wc * 8) * 2,
                       Wb + (size_t)wrw * N + wc * 8);
        }
        cp_commit();
    };

    issue(0);
    issue(1);

    const int niter = K / 32;
    for (int kt = 0; kt < niter; kt++) {
        if (kt + 2 <= niter) cp_wait1(); else cp_wait0();
        __syncthreads();
        if (kt + 2 < niter) issue(kt + 2);

        const int st = kt % 3;
        const u32 a_st = as_base + st * A_STAGE * 2;
        const u32 w_st = ws_base + st * W_STAGE * 2;

#pragma unroll
        for (int ks = 0; ks < 2; ks++) {
            u32 af[4][4];
#pragma unroll
            for (int mt = 0; mt < 4; mt++) {
                u32 addr = a_st +
                    ((wm0 + mt * 16 + a_row_off) * AS_LD + ks * 16 + a_col_off) * 2;
                ldm_x4(af[mt][0], af[mt][1], af[mt][2], af[mt][3], addr);
            }
            u32 b0[4], b1[4];
#pragma unroll
            for (int nb = 0; nb < 2; nb++) {
                u32 addr = w_st +
                    ((16 * ks + (lane & 15)) * WS_LD + wn0 + 16 * nb + (lane >> 4) * 8) * 2;
                ldm_x4t(b0[2 * nb], b1[2 * nb], b0[2 * nb + 1], b1[2 * nb + 1], addr);
            }
#pragma unroll
            for (int mt = 0; mt < 4; mt++)
#pragma unroll
                for (int nt = 0; nt < 4; nt++)
                    mma_f16(acc[mt][nt], af[mt], b0[nt], b1[nt]);
        }
    }
    epi(acc, wm0, wn0, gid, tig);
}

// ---------------- merged QKV projection (one launch, grid 9 x 64) -----------
__global__ __launch_bounds__(256, 2) void gemm_qkv_kernel(
    const float* __restrict__ bq, const float* __restrict__ bk,
    const float* __restrict__ bv,
    __half* __restrict__ qp, __half* __restrict__ kp, __half* __restrict__ vp)
{
    const int sel = blockIdx.x / 3;
    const int n0  = (blockIdx.x % 3) * 128;
    const int m0  = blockIdx.y * 128;
    const float* bias = (sel == 0) ? bq : ((sel == 1) ? bk : bv);
    __half* out       = (sel == 0) ? qp : ((sel == 1) ? kp : vp);
    const float oscale = (sel == 0) ? QSCALE : 1.0f;

    gemm_core_h(g_xh, g_wh[sel], CDIM, CDIM, m0, n0,
        [&](float acc[4][4][4], int wm0, int wn0, int gid, int tig) {
#pragma unroll
            for (int mt = 0; mt < 4; mt++) {
#pragma unroll
                for (int half = 0; half < 2; half++) {
                    const int m = m0 + wm0 + mt * 16 + gid + half * 8;
#pragma unroll
                    for (int nt = 0; nt < 4; nt++) {
                        const int n = n0 + wn0 + nt * 8 + 2 * tig;
                        float vx = (acc[mt][nt][half * 2 + 0] + bias[n + 0]) * oscale;
                        float vy = (acc[mt][nt][half * 2 + 1] + bias[n + 1]) * oscale;
                        const int b = m >> 11, t = m & 2047;
                        const int h = n >> 6, d = n & 63;
                        *reinterpret_cast<u32*>(
                            &out[(((size_t)(b * HEADS + h) * T_SEQ + t) * DH) + d]) =
                            pack_h2(vx, vy);
                    }
                }
            }
        });
}

// ---------------- output projection: A=ctx fp16, out float [M,N] ------------
__global__ __launch_bounds__(256, 2) void gemm_out_kernel(
    const float* __restrict__ bias, float* __restrict__ out)
{
    const int n0 = blockIdx.x * 128;
    const int m0 = blockIdx.y * 128;

    gemm_core_h(g_ctx, g_wh[3], CDIM, CDIM, m0, n0,
        [&](float acc[4][4][4], int wm0, int wn0, int gid, int tig) {
#pragma unroll
            for (int mt = 0; mt < 4; mt++) {
#pragma unroll
                for (int half = 0; half < 2; half++) {
                    const int m = m0 + wm0 + mt * 16 + gid + half * 8;
#pragma unroll
                    for (int nt = 0; nt < 4; nt++) {
                        const int n = n0 + wn0 + nt * 8 + 2 * tig;
                        *reinterpret_cast<float2*>(&out[(size_t)m * CDIM + n]) =
                            make_float2(acc[mt][nt][half * 2 + 0] + bias[n + 0],
                                        acc[mt][nt][half * 2 + 1] + bias[n + 1]);
                    }
                }
            }
        });
}

// ---------------- fp16 tensor-core causal flash attention -------------------
// BQ=128 (8 warps x 16 rows), 128-key softmax rounds, P in registers via
// ex2.approx.f16x2, row-sums via P@ones mma, 3-stage cp.async ring.
// V fragments for the first two s2-groups are prefetched BEFORE the softmax
// so their LDSM latency overlaps the softmax serial chain.
#define BQ 128
#define RK 128                        // keys per softmax round
#define KS_LD 72   // halfs
#define VS_LD 72
#define STAGE_HALFS (RK * KS_LD + RK * VS_LD)       // 18432
#define ATTN_SMEM_BYTES (3 * STAGE_HALFS * 2)       // 110592

__global__ void __launch_bounds__(256, 1) attn_kernel(__half* __restrict__ ctx)
{
    extern __shared__ __half smh[];

    const int tid  = threadIdx.x;
    const int lane = tid & 31;
    const int w    = tid >> 5;
    const int gid  = lane >> 2;
    const int tig  = lane & 3;

    const int bh = blockIdx.y;
    const int qi = gridDim.x - 1 - blockIdx.x;   // heavy blocks first
    const int q0 = qi * BQ;

    const __half* qb = g_q + (size_t)bh * T_SEQ * DH;
    const __half* kb = g_k + (size_t)bh * T_SEQ * DH;
    const __half* vb = g_v + (size_t)bh * T_SEQ * DH;

    // ---- Q A-frags straight from gmem (once per block) ----
    const int arow = w * 16 + gid;
    u32 qf[4][4];
#pragma unroll
    for (int s = 0; s < 4; s++) {
        const __half* base = &qb[(size_t)(q0 + arow) * DH + s * 16 + 2 * tig];
        qf[s][0] = *reinterpret_cast<const u32*>(base);
        qf[s][1] = *reinterpret_cast<const u32*>(base + 8 * DH);
        qf[s][2] = *reinterpret_cast<const u32*>(base + 8);
        qf[s][3] = *reinterpret_cast<const u32*>(base + 8 * DH + 8);
    }

    float O[8][4];
#pragma unroll
    for (int nt = 0; nt < 8; nt++)
#pragma unroll
        for (int j = 0; j < 4; j++) O[nt][j] = 0.f;
    float OS[4] = {0.f, 0.f, 0.f, 0.f};   // row-sum accumulator (l) via mma
    float mA = -1e30f, mB = -1e30f;

    const u32 smbase = (u32)__cvta_generic_to_shared(smh);
    u32 kbase[3], vbase[3];
#pragma unroll
    for (int s = 0; s < 3; s++) {
        kbase[s] = smbase + (s * STAGE_HALFS) * 2;
        vbase[s] = kbase[s] + (RK * KS_LD) * 2;
    }

    const int nrounds = qi + 1;

    // cp.async: 128 rows x 8 chunks per tensor per round; 4 K + 4 V per thread
    auto issue = [&](int r) {
        const int st = r % 3;
        const __half* kbr = kb + (size_t)(r * RK) * DH;
        const __half* vbr = vb + (size_t)(r * RK) * DH;
#pragma unroll
        for (int p = 0; p < 4; p++) {
            int id = tid + 256 * p;          // 0..1023
            int row = id >> 3, c = id & 7;   // 128 rows x 8 chunks
            cp_async16(kbase[st] + (row * KS_LD + c * 8) * 2,
                       kbr + (size_t)row * DH + c * 8);
            cp_async16(vbase[st] + (row * VS_LD + c * 8) * 2,
                       vbr + (size_t)row * DH + c * 8);
        }
        cp_commit();
    };

    issue(0);
    if (nrounds > 1) issue(1);

    for (int r = 0; r < nrounds; r++) {
        const int k0 = r * RK;
        if (r + 2 <= nrounds) cp_wait1(); else cp_wait0();
        __syncthreads();
        if (r + 2 < nrounds) issue(r + 2);

        const int buf = r % 3;

        // ---- S = Q K^T over 128 keys ----
        float S[16][4];
#pragma unroll
        for (int nt = 0; nt < 16; nt++)
#pragma unroll
            for (int j = 0; j < 4; j++) S[nt][j] = 0.f;
#pragma unroll
        for (int s = 0; s < 4; s++) {
#pragma unroll
            for (int p = 0; p < 8; p++) {
                u32 r0, r1, r2, r3;
                u32 addr = kbase[buf] +
                    (((16 * p + (lane & 15)) * KS_LD) + 16 * s + (lane >> 4) * 8) * 2;
                ldm_x4(r0, r1, r2, r3, addr);
                mma_f16(S[2 * p],     qf[s], r0, r2);
                mma_f16(S[2 * p + 1], qf[s], r1, r3);
            }
        }

        // ---- prefetch V fragments for s2 = 0,1 (overlaps softmax chain) ----
        u32 vf[2][4][4];
#pragma unroll
        for (int s2 = 0; s2 < 2; s2++) {
#pragma unroll
            for (int nb = 0; nb < 4; nb++) {
                u32 addr = vbase[buf] +
                    (((16 * s2 + (lane & 15)) * VS_LD) + 16 * nb + (lane >> 4) * 8) * 2;
                ldm_x4t(vf[s2][nb][0], vf[s2][nb][1], vf[s2][nb][2], vf[s2][nb][3],
                        addr);
            }
        }

        // ---- causal mask (only the diagonal round) ----
        const int rA = q0 + arow;
        const int rB = rA + 8;
        if (r == nrounds - 1) {
#pragma unroll
            for (int nt = 0; nt < 16; nt++) {
                const int c0 = k0 + nt * 8 + 2 * tig;
                if (c0     > rA) S[nt][0] = -1e30f;
                if (c0 + 1 > rA) S[nt][1] = -1e30f;
                if (c0     > rB) S[nt][2] = -1e30f;
                if (c0 + 1 > rB) S[nt][3] = -1e30f;
            }
        }

        // ---- online softmax (base 2), one round per 128 keys ----
        float mxA = -1e30f, mxB = -1e30f;
#pragma unroll
        for (int nt = 0; nt < 16; nt++) {
            mxA = fmaxf(mxA, fmaxf(S[nt][0], S[nt][1]));
            mxB = fmaxf(mxB, fmaxf(S[nt][2], S[nt][3]));
        }
        mxA = fmaxf(mxA, __shfl_xor_sync(0xffffffffu, mxA, 1));
        mxA = fmaxf(mxA, __shfl_xor_sync(0xffffffffu, mxA, 2));
        mxB = fmaxf(mxB, __shfl_xor_sync(0xffffffffu, mxB, 1));
        mxB = fmaxf(mxB, __shfl_xor_sync(0xffffffffu, mxB, 2));

        const float mnA = fmaxf(mA, mxA), mnB = fmaxf(mB, mxB);
        const float aA = ex2f(mA - mnA), aB = ex2f(mB - mnB);
        mA = mnA;  mB = mnB;
#pragma unroll
        for (int nt = 0; nt < 8; nt++) {
            O[nt][0] *= aA; O[nt][1] *= aA;
            O[nt][2] *= aB; O[nt][3] *= aB;
        }
        OS[0] *= aA; OS[1] *= aA; OS[2] *= aB; OS[3] *= aB;

        // ---- P = 2^(S - mn): pack f32 diffs, ex2 in f16x2 ----
        u32 pa[8][4];
#pragma unroll
        for (int s2 = 0; s2 < 8; s2++) {
            pa[s2][0] = ex2h2(pack_h2(S[2 * s2][0] - mnA, S[2 * s2][1] - mnA));
            pa[s2][1] = ex2h2(pack_h2(S[2 * s2][2] - mnB, S[2 * s2][3] - mnB));
            pa[s2][2] = ex2h2(pack_h2(S[2 * s2 + 1][0] - mnA, S[2 * s2 + 1][1] - mnA));
            pa[s2][3] = ex2h2(pack_h2(S[2 * s2 + 1][2] - mnB, S[2 * s2 + 1][3] - mnB));
        }

        // ---- O += P V (s2=0,1 use prefetched frags) ; OS += P @ ones ----
#pragma unroll
        for (int s2 = 0; s2 < 2; s2++) {
#pragma unroll
            for (int nb = 0; nb < 4; nb++) {
                mma_f16(O[2 * nb],     pa[s2], vf[s2][nb][0], vf[s2][nb][1]);
                mma_f16(O[2 * nb + 1], pa[s2], vf[s2][nb][2], vf[s2][nb][3]);
            }
            mma_f16(OS, pa[s2], ONES_H2, ONES_H2);
        }
#pragma unroll
        for (int s2 = 2; s2 < 8; s2++) {
#pragma unroll
            for (int nb = 0; nb < 4; nb++) {
                u32 r0, r1, r2, r3;
                u32 addr = vbase[buf] +
                    (((16 * s2 + (lane & 15)) * VS_LD) + 16 * nb + (lane >> 4) * 8) * 2;
                ldm_x4t(r0, r1, r2, r3, addr);
                mma_f16(O[2 * nb],     pa[s2], r0, r1);
                mma_f16(O[2 * nb + 1], pa[s2], r2, r3);
            }
            mma_f16(OS, pa[s2], ONES_H2, ONES_H2);
        }
    }

    // ---- epilogue: fp16 ctx ----
    const float iA = 1.f / OS[0], iB = 1.f / OS[2];
    const int b = bh / HEADS, h = bh % HEADS;
    const size_t rowA = (size_t)(b * T_SEQ + q0 + arow) * CDIM + h * DH;
    const size_t rowB = rowA + (size_t)8 * CDIM;
#pragma unroll
    for (int nt = 0; nt < 8; nt++) {
        *reinterpret_cast<u32*>(&ctx[rowA + nt * 8 + 2 * tig]) =
            pack_h2(O[nt][0] * iA, O[nt][1] * iA);
        *reinterpret_cast<u32*>(&ctx[rowB + nt * 8 + 2 * tig]) =
            pack_h2(O[nt][2] * iB, O[nt][3] * iB);
    }
}

// ---------------- launch ----------------------------------------------------
extern "C" void kernel_launch(void* const* d_in, const int* in_sizes, int n_in,
                              void* d_out, int out_size)
{
    (void)in_sizes; (void)n_in; (void)out_size;
    const float* x  = (const float*)d_in[0];
    const float* Wq = (const float*)d_in[1];
    const float* bq = (const float*)d_in[2];
    const float* Wk = (const float*)d_in[3];
    const float* bk = (const float*)d_in[4];
    const float* Wv = (const float*)d_in[5];
    const float* bv = (const float*)d_in[6];
    const float* Wo = (const float*)d_in[7];
    const float* bo = (const float*)d_in[8];
    float* out = (float*)d_out;

    static __half *xh = nullptr, *wh = nullptr, *qp = nullptr, *kp = nullptr,
                  *vp = nullptr, *cp = nullptr;
    if (!xh) {
        cudaGetSymbolAddress((void**)&xh, g_xh);
        cudaGetSymbolAddress((void**)&wh, g_wh);
        cudaGetSymbolAddress((void**)&qp, g_q);
        cudaGetSymbolAddress((void**)&kp, g_k);
        cudaGetSymbolAddress((void**)&vp, g_v);
        cudaGetSymbolAddress((void**)&cp, g_ctx);
        cudaFuncSetAttribute(attn_kernel,
                             cudaFuncAttributeMaxDynamicSharedMemorySize,
                             ATTN_SMEM_BYTES);
        cudaFuncSetAttribute(gemm_qkv_kernel,
                             cudaFuncAttributeMaxDynamicSharedMemorySize,
                             GEMM_SMEM_BYTES);
        cudaFuncSetAttribute(gemm_out_kernel,
                             cudaFuncAttributeMaxDynamicSharedMemorySize,
                             GEMM_SMEM_BYTES);
    }

    // fp32 -> fp16 converts
    cvt_x_kernel<<<MROWS * CDIM / 1024, 256>>>(x, xh);
    dim3 wgrid(CDIM * CDIM / 1024, 4);
    cvt_w_kernel<<<wgrid, 256>>>(Wq, Wk, Wv, Wo, wh);

    // merged QKV projection: grid (9, 64)
    dim3 qkvgrid(9, MROWS / 128);
    gemm_qkv_kernel<<<qkvgrid, 256, GEMM_SMEM_BYTES>>>(bq, bk, bv, qp, kp, vp);

    dim3 agrid(T_SEQ / BQ, BATCH * HEADS);   // (16, 24)
    attn_kernel<<<agrid, 256, ATTN_SMEM_BYTES>>>(cp);

    dim3 ogrid(CDIM / 128, MROWS / 128);     // (3, 64)
    gemm_out_kernel<<<ogrid, 256, GEMM_SMEM_BYTES>>>(bo, out);
}

// round 17
// speedup vs baseline: 1.0903x; 1.0683x over previous
#include <cuda_runtime.h>
#include <cuda_fp16.h>

// Problem constants
#define BATCH   4
#define T_SEQ   2048
#define CDIM    384
#define HEADS   6
#define DH      64
#define MROWS   (BATCH * T_SEQ)        // 8192

typedef unsigned int u32;

// Q pre-scale: 1/sqrt(64) * log2(e)  (base-2 softmax)
#define QSCALE (0.125f * 1.4426950408889634f)
#define ONES_H2 0x3C003C00u            // fp16 {1.0, 1.0}

// ---------------- scratch (static device globals; no runtime allocation) ----
__device__ __half g_xh[MROWS * CDIM];               // x in fp16
__device__ __half g_wh[4][CDIM * CDIM];             // Wq,Wk,Wv,Wo in fp16
__device__ __half g_q[BATCH * HEADS * T_SEQ * DH];  // [B,H,T,D], pre-scaled
__device__ __half g_k[BATCH * HEADS * T_SEQ * DH];
__device__ __half g_v[BATCH * HEADS * T_SEQ * DH];
__device__ __half g_ctx[MROWS * CDIM];              // [B*T, C] fp16

// ---------------- primitives ------------------------------------------------
__device__ __forceinline__ u32 pack_h2(float lo, float hi) {
    u32 r;
    asm("cvt.rn.f16x2.f32 %0, %1, %2;" : "=r"(r) : "f"(hi), "f"(lo));
    return r;
}
__device__ __forceinline__ float ex2f(float x) {
    float y;
    asm("ex2.approx.f32 %0, %1;" : "=f"(y) : "f"(x));
    return y;
}
__device__ __forceinline__ u32 ex2h2(u32 x) {
    u32 y;
    asm("ex2.approx.f16x2 %0, %1;" : "=r"(y) : "r"(x));
    return y;
}

__device__ __forceinline__ void mma_f16(float c[4], const u32 a[4], u32 b0, u32 b1) {
    asm volatile(
        "mma.sync.aligned.m16n8k16.row.col.f32.f16.f16.f32 "
        "{%0,%1,%2,%3}, {%4,%5,%6,%7}, {%8,%9}, {%0,%1,%2,%3};\n"
        : "+f"(c[0]), "+f"(c[1]), "+f"(c[2]), "+f"(c[3])
        : "r"(a[0]), "r"(a[1]), "r"(a[2]), "r"(a[3]), "r"(b0), "r"(b1));
}

__device__ __forceinline__ void ldm_x4(u32& r0, u32& r1, u32& r2, u32& r3, u32 addr) {
    asm volatile("ldmatrix.sync.aligned.m8n8.x4.shared.b16 {%0,%1,%2,%3}, [%4];"
                 : "=r"(r0), "=r"(r1), "=r"(r2), "=r"(r3) : "r"(addr));
}
__device__ __forceinline__ void ldm_x4t(u32& r0, u32& r1, u32& r2, u32& r3, u32 addr) {
    asm volatile("ldmatrix.sync.aligned.m8n8.x4.trans.shared.b16 {%0,%1,%2,%3}, [%4];"
                 : "=r"(r0), "=r"(r1), "=r"(r2), "=r"(r3) : "r"(addr));
}

__device__ __forceinline__ void cp_async16(u32 saddr, const void* gptr) {
    asm volatile("cp.async.cg.shared.global [%0], [%1], 16;" :: "r"(saddr), "l"(gptr));
}
__device__ __forceinline__ void cp_commit() { asm volatile("cp.async.commit_group;"); }
__device__ __forceinline__ void cp_wait1()  { asm volatile("cp.async.wait_group 1;"); }
__device__ __forceinline__ void cp_wait0()  { asm volatile("cp.async.wait_group 0;"); }

// ---------------- mbarrier primitives ----------------------------------------
__device__ __forceinline__ void mbar_init(u32 a, u32 cnt) {
    asm volatile("mbarrier.init.shared.b64 [%0], %1;" :: "r"(a), "r"(cnt) : "memory");
}
__device__ __forceinline__ void mbar_arrive(u32 a) {
    asm volatile("mbarrier.arrive.shared.b64 _, [%0];" :: "r"(a) : "memory");
}
__device__ __forceinline__ void cp_mbar_arrive_noinc(u32 a) {
    asm volatile("cp.async.mbarrier.arrive.noinc.shared.b64 [%0];"
                 :: "r"(a) : "memory");
}
__device__ __forceinline__ void mbar_wait(u32 mbar, u32 parity) {
    asm volatile(
        "{\n\t.reg .pred P1;\n\t"
        "WAIT_LOOP_%=:\n\t"
        "mbarrier.try_wait.parity.acquire.cta.shared::cta.b64 P1, [%0], %1, 0x989680;\n\t"
        "@P1 bra.uni WAIT_DONE_%=;\n\t"
        "bra.uni WAIT_LOOP_%=;\n\t"
        "WAIT_DONE_%=:\n\t}"
        :: "r"(mbar), "r"(parity) : "memory");
}

// ---------------- fp32 -> fp16 converters -----------------------------------
__global__ __launch_bounds__(256) void cvt_x_kernel(const float* __restrict__ in,
                                                    __half* __restrict__ out) {
    int i = (blockIdx.x * 256 + threadIdx.x) * 4;
    float4 v = *reinterpret_cast<const float4*>(in + i);
    *reinterpret_cast<uint2*>(out + i) =
        make_uint2(pack_h2(v.x, v.y), pack_h2(v.z, v.w));
}
__global__ __launch_bounds__(256) void cvt_w_kernel(
    const float* __restrict__ w0, const float* __restrict__ w1,
    const float* __restrict__ w2, const float* __restrict__ w3,
    __half* __restrict__ out) {
    const float* src = (blockIdx.y == 0) ? w0 : (blockIdx.y == 1) ? w1
                     : (blockIdx.y == 2) ? w2 : w3;
    int i = (blockIdx.x * 256 + threadIdx.x) * 4;
    float4 v = *reinterpret_cast<const float4*>(src + i);
    *reinterpret_cast<uint2*>(out + blockIdx.y * (CDIM * CDIM) + i) =
        make_uint2(pack_h2(v.x, v.y), pack_h2(v.z, v.w));
}

// ---------------- fp16 GEMM core: cp.async 3-stage, 128x128 tile, BK=32 -----
#define AS_LD 40    // halfs
#define WS_LD 136   // halfs
#define A_STAGE (128 * AS_LD)   // 5120 halfs
#define W_STAGE (32 * WS_LD)    // 4352 halfs
#define GEMM_SMEM_BYTES (3 * (A_STAGE + W_STAGE) * 2)   // 56832

template <typename EPI>
__device__ __forceinline__ void gemm_core_h(
    const __half* __restrict__ A, const __half* __restrict__ W,
    int K, int N, int m0, int n0, EPI epi)
{
    extern __shared__ __half sh[];
    __half* As = sh;
    __half* Ws = sh + 3 * A_STAGE;

    const int tid  = threadIdx.x;
    const int lane = tid & 31;
    const int w    = tid >> 5;
    const int gid  = lane >> 2;
    const int tig  = lane & 3;
    const int wm0  = (w & 1) * 64;
    const int wn0  = (w >> 1) * 32;
    const u32 as_base = (u32)__cvta_generic_to_shared(As);
    const u32 ws_base = (u32)__cvta_generic_to_shared(Ws);

    const int a_id = lane >> 3;
    const int a_r  = lane & 7;
    const int a_row_off = (a_id & 1) * 8 + a_r;
    const int a_col_off = (a_id >> 1) * 8;

    float acc[4][4][4];
#pragma unroll
    for (int mt = 0; mt < 4; mt++)
#pragma unroll
        for (int nt = 0; nt < 4; nt++)
#pragma unroll
            for (int j = 0; j < 4; j++) acc[mt][nt][j] = 0.f;

    auto issue = [&](int kt) {
        const int st = kt % 3;
        const __half* Ab = A + (size_t)m0 * K + kt * 32;
        const __half* Wb = W + (size_t)(kt * 32) * N + n0;
#pragma unroll
        for (int p = 0; p < 2; p++) {
            int id = tid + 256 * p;
            int arw = id >> 2, ac = id & 3;
            cp_async16(as_base + (st * A_STAGE + arw * AS_LD + ac * 8) * 2,
                       Ab + (size_t)arw * K + ac * 8);
            int wrw = id >> 4, wc = id & 15;
            cp_async16(ws_base + (st * W_STAGE + wrw * WS_LD + wc * 8) * 2,
                       Wb + (size_t)wrw * N + wc * 8);
        }
        cp_commit();
    };

    issue(0);
    issue(1);

    const int niter = K / 32;
    for (int kt = 0; kt < niter; kt++) {
        if (kt + 2 <= niter) cp_wait1(); else cp_wait0();
        __syncthreads();
        if (kt + 2 < niter) issue(kt + 2);

        const int st = kt % 3;
        const u32 a_st = as_base + st * A_STAGE * 2;
        const u32 w_st = ws_base + st * W_STAGE * 2;

#pragma unroll
        for (int ks = 0; ks < 2; ks++) {
            u32 af[4][4];
#pragma unroll
            for (int mt = 0; mt < 4; mt++) {
                u32 addr = a_st +
                    ((wm0 + mt * 16 + a_row_off) * AS_LD + ks * 16 + a_col_off) * 2;
                ldm_x4(af[mt][0], af[mt][1], af[mt][2], af[mt][3], addr);
            }
            u32 b0[4], b1[4];
#pragma unroll
            for (int nb = 0; nb < 2; nb++) {
                u32 addr = w_st +
                    ((16 * ks + (lane & 15)) * WS_LD + wn0 + 16 * nb + (lane >> 4) * 8) * 2;
                ldm_x4t(b0[2 * nb], b1[2 * nb], b0[2 * nb + 1], b1[2 * nb + 1], addr);
            }
#pragma unroll
            for (int mt = 0; mt < 4; mt++)
#pragma unroll
                for (int nt = 0; nt < 4; nt++)
                    mma_f16(acc[mt][nt], af[mt], b0[nt], b1[nt]);
        }
    }
    epi(acc, wm0, wn0, gid, tig);
}

// ---------------- merged QKV projection (one launch, grid 9 x 64) -----------
__global__ __launch_bounds__(256, 2) void gemm_qkv_kernel(
    const float* __restrict__ bq, const float* __restrict__ bk,
    const float* __restrict__ bv,
    __half* __restrict__ qp, __half* __restrict__ kp, __half* __restrict__ vp)
{
    const int sel = blockIdx.x / 3;
    const int n0  = (blockIdx.x % 3) * 128;
    const int m0  = blockIdx.y * 128;
    const float* bias = (sel == 0) ? bq : ((sel == 1) ? bk : bv);
    __half* out       = (sel == 0) ? qp : ((sel == 1) ? kp : vp);
    const float oscale = (sel == 0) ? QSCALE : 1.0f;

    gemm_core_h(g_xh, g_wh[sel], CDIM, CDIM, m0, n0,
        [&](float acc[4][4][4], int wm0, int wn0, int gid, int tig) {
#pragma unroll
            for (int mt = 0; mt < 4; mt++) {
#pragma unroll
                for (int half = 0; half < 2; half++) {
                    const int m = m0 + wm0 + mt * 16 + gid + half * 8;
#pragma unroll
                    for (int nt = 0; nt < 4; nt++) {
                        const int n = n0 + wn0 + nt * 8 + 2 * tig;
                        float vx = (acc[mt][nt][half * 2 + 0] + bias[n + 0]) * oscale;
                        float vy = (acc[mt][nt][half * 2 + 1] + bias[n + 1]) * oscale;
                        const int b = m >> 11, t = m & 2047;
                        const int h = n >> 6, d = n & 63;
                        *reinterpret_cast<u32*>(
                            &out[(((size_t)(b * HEADS + h) * T_SEQ + t) * DH) + d]) =
                            pack_h2(vx, vy);
                    }
                }
            }
        });
}

// ---------------- output projection: A=ctx fp16, out float [M,N] ------------
__global__ __launch_bounds__(256, 2) void gemm_out_kernel(
    const float* __restrict__ bias, float* __restrict__ out)
{
    const int n0 = blockIdx.x * 128;
    const int m0 = blockIdx.y * 128;

    gemm_core_h(g_ctx, g_wh[3], CDIM, CDIM, m0, n0,
        [&](float acc[4][4][4], int wm0, int wn0, int gid, int tig) {
#pragma unroll
            for (int mt = 0; mt < 4; mt++) {
#pragma unroll
                for (int half = 0; half < 2; half++) {
                    const int m = m0 + wm0 + mt * 16 + gid + half * 8;
#pragma unroll
                    for (int nt = 0; nt < 4; nt++) {
                        const int n = n0 + wn0 + nt * 8 + 2 * tig;
                        *reinterpret_cast<float2*>(&out[(size_t)m * CDIM + n]) =
                            make_float2(acc[mt][nt][half * 2 + 0] + bias[n + 0],
                                        acc[mt][nt][half * 2 + 1] + bias[n + 1]);
                    }
                }
            }
        });
}

// ---------------- fp16 causal flash attention: warp-specialized -------------
// 320 threads: warps 0-7 consume (16 q-rows each), warps 8-9 produce (cp.async
// K/V into a 3-stage ring). full[s] (cnt 64, cp.async.mbarrier.arrive.noinc) /
// empty[s] (cnt 256) replace __syncthreads -- consumer warps free-run.
#define BQ 128
#define RK 128                        // keys per softmax round
#define KS_LD 72   // halfs
#define VS_LD 72
#define STAGE_HALFS (RK * KS_LD + RK * VS_LD)       // 18432
#define ATTN_SMEM_BYTES (3 * STAGE_HALFS * 2)       // 110592

__global__ void __launch_bounds__(320, 1) attn_kernel(__half* __restrict__ ctx)
{
    extern __shared__ __half smh[];
    __shared__ __align__(8) unsigned long long s_full[3], s_empty[3];

    const int tid  = threadIdx.x;
    const int lane = tid & 31;
    const int w    = tid >> 5;           // 0..9

    const int bh = blockIdx.y;
    const int qi = gridDim.x - 1 - blockIdx.x;   // heavy blocks first
    const int q0 = qi * BQ;

    const __half* qb = g_q + (size_t)bh * T_SEQ * DH;
    const __half* kb = g_k + (size_t)bh * T_SEQ * DH;
    const __half* vb = g_v + (size_t)bh * T_SEQ * DH;

    const u32 smbase = (u32)__cvta_generic_to_shared(smh);
    u32 kbase[3], vbase[3], mbf[3], mbe[3];
#pragma unroll
    for (int s = 0; s < 3; s++) {
        kbase[s] = smbase + (s * STAGE_HALFS) * 2;
        vbase[s] = kbase[s] + (RK * KS_LD) * 2;
        mbf[s] = (u32)__cvta_generic_to_shared(&s_full[s]);
        mbe[s] = (u32)__cvta_generic_to_shared(&s_empty[s]);
    }

    if (tid == 0) {
#pragma unroll
        for (int s = 0; s < 3; s++) {
            mbar_init(mbf[s], 64);    // 2 producer warps x 32 threads (noinc)
            mbar_init(mbe[s], 256);   // 8 consumer warps x 32 lanes
        }
    }
    __syncthreads();

    const int nrounds = qi + 1;

    if (w >= 8) {
        // ================= producer warps =================
        const int ptid = tid - 256;          // 0..63
        int pst = 0, pph = 1;                // empty-wait cursor (phase starts 1)
        for (int r = 0; r < nrounds; r++) {
            mbar_wait(mbe[pst], (u32)pph);
            const __half* kbr = kb + (size_t)(r * RK) * DH;
            const __half* vbr = vb + (size_t)(r * RK) * DH;
#pragma unroll
            for (int p = 0; p < 16; p++) {
                int id = ptid + 64 * p;          // 0..1023
                int row = id >> 3, c = id & 7;   // 128 rows x 8 chunks
                cp_async16(kbase[pst] + (row * KS_LD + c * 8) * 2,
                           kbr + (size_t)row * DH + c * 8);
                cp_async16(vbase[pst] + (row * VS_LD + c * 8) * 2,
                           vbr + (size_t)row * DH + c * 8);
            }
            cp_mbar_arrive_noinc(mbf[pst]);
            if (++pst == 3) { pst = 0; pph ^= 1; }
        }
        return;
    }

    // ================= consumer warps (w = 0..7) =================
    const int gid  = lane >> 2;
    const int tig  = lane & 3;
    const int arow = w * 16 + gid;

    u32 qf[4][4];
#pragma unroll
    for (int s = 0; s < 4; s++) {
        const __half* base = &qb[(size_t)(q0 + arow) * DH + s * 16 + 2 * tig];
        qf[s][0] = *reinterpret_cast<const u32*>(base);
        qf[s][1] = *reinterpret_cast<const u32*>(base + 8 * DH);
        qf[s][2] = *reinterpret_cast<const u32*>(base + 8);
        qf[s][3] = *reinterpret_cast<const u32*>(base + 8 * DH + 8);
    }

    float O[8][4];
#pragma unroll
    for (int nt = 0; nt < 8; nt++)
#pragma unroll
        for (int j = 0; j < 4; j++) O[nt][j] = 0.f;
    float OS[4] = {0.f, 0.f, 0.f, 0.f};
    float mA = -1e30f, mB = -1e30f;

    int cst = 0, cph = 0;                    // full-wait cursor
    for (int r = 0; r < nrounds; r++) {
        const int k0 = r * RK;
        mbar_wait(mbf[cst], (u32)cph);
        const int buf = cst;

        // ---- S = Q K^T over 128 keys ----
        float S[16][4];
#pragma unroll
        for (int nt = 0; nt < 16; nt++)
#pragma unroll
            for (int j = 0; j < 4; j++) S[nt][j] = 0.f;
#pragma unroll
        for (int s = 0; s < 4; s++) {
#pragma unroll
            for (int p = 0; p < 8; p++) {
                u32 r0, r1, r2, r3;
                u32 addr = kbase[buf] +
                    (((16 * p + (lane & 15)) * KS_LD) + 16 * s + (lane >> 4) * 8) * 2;
                ldm_x4(r0, r1, r2, r3, addr);
                mma_f16(S[2 * p],     qf[s], r0, r2);
                mma_f16(S[2 * p + 1], qf[s], r1, r3);
            }
        }

        // ---- prefetch V fragments for s2 = 0,1 (overlaps softmax chain) ----
        u32 vf[2][4][4];
#pragma unroll
        for (int s2 = 0; s2 < 2; s2++) {
#pragma unroll
            for (int nb = 0; nb < 4; nb++) {
                u32 addr = vbase[buf] +
                    (((16 * s2 + (lane & 15)) * VS_LD) + 16 * nb + (lane >> 4) * 8) * 2;
                ldm_x4t(vf[s2][nb][0], vf[s2][nb][1], vf[s2][nb][2], vf[s2][nb][3],
                        addr);
            }
        }

        // ---- causal mask (only the diagonal round) ----
        const int rA = q0 + arow;
        const int rB = rA + 8;
        if (r == nrounds - 1) {
#pragma unroll
            for (int nt = 0; nt < 16; nt++) {
                const int c0 = k0 + nt * 8 + 2 * tig;
                if (c0     > rA) S[nt][0] = -1e30f;
                if (c0 + 1 > rA) S[nt][1] = -1e30f;
                if (c0     > rB) S[nt][2] = -1e30f;
                if (c0 + 1 > rB) S[nt][3] = -1e30f;
            }
        }

        // ---- online softmax (base 2) ----
        float mxA = -1e30f, mxB = -1e30f;
#pragma unroll
        for (int nt = 0; nt < 16; nt++) {
            mxA = fmaxf(mxA, fmaxf(S[nt][0], S[nt][1]));
            mxB = fmaxf(mxB, fmaxf(S[nt][2], S[nt][3]));
        }
        mxA = fmaxf(mxA, __shfl_xor_sync(0xffffffffu, mxA, 1));
        mxA = fmaxf(mxA, __shfl_xor_sync(0xffffffffu, mxA, 2));
        mxB = fmaxf(mxB, __shfl_xor_sync(0xffffffffu, mxB, 1));
        mxB = fmaxf(mxB, __shfl_xor_sync(0xffffffffu, mxB, 2));

        const float mnA = fmaxf(mA, mxA), mnB = fmaxf(mB, mxB);
        const float aA = ex2f(mA - mnA), aB = ex2f(mB - mnB);
        mA = mnA;  mB = mnB;
#pragma unroll
        for (int nt = 0; nt < 8; nt++) {
            O[nt][0] *= aA; O[nt][1] *= aA;
            O[nt][2] *= aB; O[nt][3] *= aB;
        }
        OS[0] *= aA; OS[1] *= aA; OS[2] *= aB; OS[3] *= aB;

        // ---- P = 2^(S - mn): pack f32 diffs, ex2 in f16x2 ----
        u32 pa[8][4];
#pragma unroll
        for (int s2 = 0; s2 < 8; s2++) {
            pa[s2][0] = ex2h2(pack_h2(S[2 * s2][0] - mnA, S[2 * s2][1] - mnA));
            pa[s2][1] = ex2h2(pack_h2(S[2 * s2][2] - mnB, S[2 * s2][3] - mnB));
            pa[s2][2] = ex2h2(pack_h2(S[2 * s2 + 1][0] - mnA, S[2 * s2 + 1][1] - mnA));
            pa[s2][3] = ex2h2(pack_h2(S[2 * s2 + 1][2] - mnB, S[2 * s2 + 1][3] - mnB));
        }

        // ---- O += P V ; OS += P @ ones ----
#pragma unroll
        for (int s2 = 0; s2 < 2; s2++) {
#pragma unroll
            for (int nb = 0; nb < 4; nb++) {
                mma_f16(O[2 * nb],     pa[s2], vf[s2][nb][0], vf[s2][nb][1]);
                mma_f16(O[2 * nb + 1], pa[s2], vf[s2][nb][2], vf[s2][nb][3]);
            }
            mma_f16(OS, pa[s2], ONES_H2, ONES_H2);
        }
#pragma unroll
        for (int s2 = 2; s2 < 8; s2++) {
#pragma unroll
            for (int nb = 0; nb < 4; nb++) {
                u32 r0, r1, r2, r3;
                u32 addr = vbase[buf] +
                    (((16 * s2 + (lane & 15)) * VS_LD) + 16 * nb + (lane >> 4) * 8) * 2;
                ldm_x4t(r0, r1, r2, r3, addr);
                mma_f16(O[2 * nb],     pa[s2], r0, r1);
                mma_f16(O[2 * nb + 1], pa[s2], r2, r3);
            }
            mma_f16(OS, pa[s2], ONES_H2, ONES_H2);
        }

        // stage consumed -> signal empty
        mbar_arrive(mbe[cst]);
        if (++cst == 3) { cst = 0; cph ^= 1; }
    }

    // ---- epilogue: fp16 ctx ----
    const float iA = 1.f / OS[0], iB = 1.f / OS[2];
    const int b = bh / HEADS, h = bh % HEADS;
    const size_t rowA = (size_t)(b * T_SEQ + q0 + arow) * CDIM + h * DH;
    const size_t rowB = rowA + (size_t)8 * CDIM;
#pragma unroll
    for (int nt = 0; nt < 8; nt++) {
        *reinterpret_cast<u32*>(&ctx[rowA + nt * 8 + 2 * tig]) =
            pack_h2(O[nt][0] * iA, O[nt][1] * iA);
        *reinterpret_cast<u32*>(&ctx[rowB + nt * 8 + 2 * tig]) =
            pack_h2(O[nt][2] * iB, O[nt][3] * iB);
    }
}

// ---------------- launch ----------------------------------------------------
extern "C" void kernel_launch(void* const* d_in, const int* in_sizes, int n_in,
                              void* d_out, int out_size)
{
    (void)in_sizes; (void)n_in; (void)out_size;
    const float* x  = (const float*)d_in[0];
    const float* Wq = (const float*)d_in[1];
    const float* bq = (const float*)d_in[2];
    const float* Wk = (const float*)d_in[3];
    const float* bk = (const float*)d_in[4];
    const float* Wv = (const float*)d_in[5];
    const float* bv = (const float*)d_in[6];
    const float* Wo = (const float*)d_in[7];
    const float* bo = (const float*)d_in[8];
    float* out = (float*)d_out;

    static __half *xh = nullptr, *wh = nullptr, *qp = nullptr, *kp = nullptr,
                  *vp = nullptr, *cp = nullptr;
    if (!xh) {
        cudaGetSymbolAddress((void**)&xh, g_xh);
        cudaGetSymbolAddress((void**)&wh, g_wh);
        cudaGetSymbolAddress((void**)&qp, g_q);
        cudaGetSymbolAddress((void**)&kp, g_k);
        cudaGetSymbolAddress((void**)&vp, g_v);
        cudaGetSymbolAddress((void**)&cp, g_ctx);
        cudaFuncSetAttribute(attn_kernel,
                             cudaFuncAttributeMaxDynamicSharedMemorySize,
                             ATTN_SMEM_BYTES);
        cudaFuncSetAttribute(gemm_qkv_kernel,
                             cudaFuncAttributeMaxDynamicSharedMemorySize,
                             GEMM_SMEM_BYTES);
        cudaFuncSetAttribute(gemm_out_kernel,
                             cudaFuncAttributeMaxDynamicSharedMemorySize,
                             GEMM_SMEM_BYTES);
    }

    // fp32 -> fp16 converts
    cvt_x_kernel<<<MROWS * CDIM / 1024, 256>>>(x, xh);
    dim3 wgrid(CDIM * CDIM / 1024, 4);
    cvt_w_kernel<<<wgrid, 256>>>(Wq, Wk, Wv, Wo, wh);

    // merged QKV projection: grid (9, 64)
    dim3 qkvgrid(9, MROWS / 128);
    gemm_qkv_kernel<<<qkvgrid, 256, GEMM_SMEM_BYTES>>>(bq, bk, bv, qp, kp, vp);

    dim3 agrid(T_SEQ / BQ, BATCH * HEADS);   // (16, 24)
    attn_kernel<<<agrid, 320, ATTN_SMEM_BYTES>>>(cp);

    dim3 ogrid(CDIM / 128, MROWS / 128);     // (3, 64)
    gemm_out_kernel<<<ogrid, 256, GEMM_SMEM_BYTES>>>(bo, out);
}